// round 1
// baseline (speedup 1.0000x reference)
#include <cuda_runtime.h>

#define CC   64
#define CC2  32
#define TT   8
#define PP   2304
#define NBT  16

// scratch: theta^T [bt][p][32], phi^T [bt][p][32], v=(out_w @ x) [bt][p][64]
__device__ float g_theta[NBT * PP * CC2];
__device__ float g_phi  [NBT * PP * CC2];
__device__ float g_v    [NBT * PP * CC ];

__device__ __forceinline__ float ex2(float x) {
    float y;
    asm("ex2.approx.ftz.f32 %0, %1;" : "=f"(y) : "f"(x));
    return y;
}

// ---------------------------------------------------------------------------
// Kernel A: per-(b,t) channel projections. theta/phi (32x64) and out_w (64x64)
// applied to every spatial point p. out_w is folded into V here so the flash
// kernel's PV output is already the final pre-residual activation.
// grid = (16, 9), block = 256 (one p per thread), dyn smem = 96KB
// ---------------------------------------------------------------------------
__global__ void prep_kernel(const float* __restrict__ x_in,
                            const float* __restrict__ thw,
                            const float* __restrict__ phw,
                            const float* __restrict__ ow) {
    extern __shared__ float sm[];
    float* xs = sm;              // [64][256]
    float* w  = sm + CC * 256;   // [128][64]: rows 0-31 theta, 32-63 phi, 64-127 out_w

    int bt = blockIdx.x, b = bt >> 3, t = bt & 7;
    int p0 = blockIdx.y * 256;
    int tid = threadIdx.x;

    for (int c = 0; c < CC; ++c)
        xs[c * 256 + tid] = x_in[((b * CC + c) * TT + t) * PP + p0 + tid];
    for (int i = tid; i < CC2 * CC; i += 256) {
        w[i]             = thw[t * CC2 * CC + i];
        w[CC2 * CC + i]  = phw[t * CC2 * CC + i];
    }
    for (int i = tid; i < CC * CC; i += 256)
        w[2 * CC2 * CC + i] = ow[i];
    __syncthreads();

    int p    = p0 + tid;
    int base = bt * PP + p;

    float acc[8];
    for (int g = 0; g < 16; ++g) {
        #pragma unroll
        for (int u = 0; u < 8; ++u) acc[u] = 0.f;
        const float* wr = &w[(g * 8) * CC];
        #pragma unroll 8
        for (int c = 0; c < CC; ++c) {
            float xc = xs[c * 256 + tid];
            #pragma unroll
            for (int u = 0; u < 8; ++u)
                acc[u] = fmaf(wr[u * CC + c], xc, acc[u]);
        }
        float4 v0 = make_float4(acc[0], acc[1], acc[2], acc[3]);
        float4 v1 = make_float4(acc[4], acc[5], acc[6], acc[7]);
        int r = g * 8;
        float4* dst;
        if (r < CC2)            dst = (float4*)&g_theta[(size_t)base * CC2 + r];
        else if (r < 2 * CC2)   dst = (float4*)&g_phi  [(size_t)base * CC2 + (r - CC2)];
        else                    dst = (float4*)&g_v    [(size_t)base * CC  + (r - 2 * CC2)];
        dst[0] = v0; dst[1] = v1;
    }
}

// ---------------------------------------------------------------------------
// Kernel B: fused flash attention per (b,t, q-tile of 128), fp32 SIMT.
// 512 threads: warp = ty (0..15), lane = tx (0..31).
// Each thread owns S rows {ty+16k} x cols {tx+32j}, O rows {ty+16k} x cols {2tx,2tx+1}.
// Softmax done in base-2; scale*log2(e) folded into Q at load time.
// Epilogue: O transposed via smem, residual added, coalesced store to BCTHW.
// grid = (18, 16), dyn smem = 134KB
// ---------------------------------------------------------------------------
__global__ void __launch_bounds__(512, 1)
flash_kernel(const float* __restrict__ x_in, float* __restrict__ out) {
    extern __shared__ float sm[];
    float* Qs = sm;                      // [128][36]
    float* Ks = Qs + 128 * 36;           // [128][36]
    float* Vs = Ks + 128 * 36;           // [128][64]
    float* Ps = Vs + 128 * 64;           // [128][132] (reused as O^T [64][132] in epilogue)

    int bt = blockIdx.y, b = bt >> 3, t = bt & 7;
    int q0 = blockIdx.x * 128;
    int tid = threadIdx.x;
    int tx = tid & 31, ty = tid >> 5;
    int base = bt * PP;

    const float scale2 = 0.17677669529663689f * 1.4426950408889634f; // (1/sqrt(32)) * log2(e)

    // load Q tile (scaled)
    for (int i = tid; i < 1024; i += 512) {
        int r = i >> 3, c4 = (i & 7) << 2;
        float4 qv = *(const float4*)&g_theta[(size_t)(base + q0 + r) * CC2 + c4];
        qv.x *= scale2; qv.y *= scale2; qv.z *= scale2; qv.w *= scale2;
        *(float4*)&Qs[r * 36 + c4] = qv;
    }

    float O0[8], O1[8], m[8], l[8];
    #pragma unroll
    for (int k = 0; k < 8; ++k) { O0[k] = 0.f; O1[k] = 0.f; m[k] = -1e30f; l[k] = 0.f; }
    __syncthreads();

    for (int kt = 0; kt < PP / 128; ++kt) {
        int k0 = kt * 128;
        // stage K (phi) and V tiles
        for (int i = tid; i < 1024; i += 512) {
            int r = i >> 3, c4 = (i & 7) << 2;
            *(float4*)&Ks[r * 36 + c4] =
                *(const float4*)&g_phi[(size_t)(base + k0 + r) * CC2 + c4];
        }
        for (int i = tid; i < 2048; i += 512) {
            int r = i >> 4, c4 = (i & 15) << 2;
            *(float4*)&Vs[r * 64 + c4] =
                *(const float4*)&g_v[(size_t)(base + k0 + r) * CC + c4];
        }
        __syncthreads();

        // S = Q * K^T  (already in log2 domain due to folded scale)
        float acc[8][4];
        #pragma unroll
        for (int k = 0; k < 8; ++k)
            #pragma unroll
            for (int j = 0; j < 4; ++j) acc[k][j] = 0.f;

        #pragma unroll
        for (int c = 0; c < 32; c += 4) {
            float4 b0 = *(float4*)&Ks[(tx      ) * 36 + c];
            float4 b1 = *(float4*)&Ks[(tx +  32) * 36 + c];
            float4 b2 = *(float4*)&Ks[(tx +  64) * 36 + c];
            float4 b3 = *(float4*)&Ks[(tx +  96) * 36 + c];
            #pragma unroll
            for (int k = 0; k < 8; ++k) {
                float4 a = *(float4*)&Qs[(ty + 16 * k) * 36 + c];
                acc[k][0] = fmaf(a.x,b0.x, fmaf(a.y,b0.y, fmaf(a.z,b0.z, fmaf(a.w,b0.w, acc[k][0]))));
                acc[k][1] = fmaf(a.x,b1.x, fmaf(a.y,b1.y, fmaf(a.z,b1.z, fmaf(a.w,b1.w, acc[k][1]))));
                acc[k][2] = fmaf(a.x,b2.x, fmaf(a.y,b2.y, fmaf(a.z,b2.z, fmaf(a.w,b2.w, acc[k][2]))));
                acc[k][3] = fmaf(a.x,b3.x, fmaf(a.y,b3.y, fmaf(a.z,b3.z, fmaf(a.w,b3.w, acc[k][3]))));
            }
        }

        // online softmax (base-2), write P tile to smem
        #pragma unroll
        for (int k = 0; k < 8; ++k) {
            float mx = fmaxf(fmaxf(acc[k][0], acc[k][1]), fmaxf(acc[k][2], acc[k][3]));
            #pragma unroll
            for (int off = 16; off > 0; off >>= 1)
                mx = fmaxf(mx, __shfl_xor_sync(0xffffffffu, mx, off));
            float mn    = fmaxf(m[k], mx);
            float alpha = ex2(m[k] - mn);
            float s = 0.f;
            #pragma unroll
            for (int j = 0; j < 4; ++j) {
                float pj = ex2(acc[k][j] - mn);
                acc[k][j] = pj;
                s += pj;
            }
            #pragma unroll
            for (int off = 16; off > 0; off >>= 1)
                s += __shfl_xor_sync(0xffffffffu, s, off);
            l[k] = l[k] * alpha + s;
            m[k] = mn;
            O0[k] *= alpha; O1[k] *= alpha;
            int row = (ty + 16 * k) * 132;
            Ps[row + tx     ] = acc[k][0];
            Ps[row + tx + 32] = acc[k][1];
            Ps[row + tx + 64] = acc[k][2];
            Ps[row + tx + 96] = acc[k][3];
        }
        __syncthreads();

        // O += P * V
        #pragma unroll 2
        for (int j = 0; j < 128; j += 4) {
            float2 v0 = *(float2*)&Vs[(j    ) * 64 + 2 * tx];
            float2 v1 = *(float2*)&Vs[(j + 1) * 64 + 2 * tx];
            float2 v2 = *(float2*)&Vs[(j + 2) * 64 + 2 * tx];
            float2 v3 = *(float2*)&Vs[(j + 3) * 64 + 2 * tx];
            #pragma unroll
            for (int k = 0; k < 8; ++k) {
                float4 p4 = *(float4*)&Ps[(ty + 16 * k) * 132 + j];
                O0[k] = fmaf(p4.x, v0.x, O0[k]); O1[k] = fmaf(p4.x, v0.y, O1[k]);
                O0[k] = fmaf(p4.y, v1.x, O0[k]); O1[k] = fmaf(p4.y, v1.y, O1[k]);
                O0[k] = fmaf(p4.z, v2.x, O0[k]); O1[k] = fmaf(p4.z, v2.y, O1[k]);
                O0[k] = fmaf(p4.w, v3.x, O0[k]); O1[k] = fmaf(p4.w, v3.y, O1[k]);
            }
        }
        __syncthreads();
    }

    // normalize and transpose O through smem for coalesced output
    #pragma unroll
    for (int k = 0; k < 8; ++k) {
        float inv = 1.f / l[k];
        O0[k] *= inv; O1[k] *= inv;
    }
    #pragma unroll
    for (int k = 0; k < 8; ++k) {
        int r = ty + 16 * k;
        Ps[(2 * tx    ) * 132 + r] = O0[k];
        Ps[(2 * tx + 1) * 132 + r] = O1[k];
    }
    __syncthreads();

    // out[b, o, t, p] = O^T[o][p-q0] + x_in[b, o, t, p]
    for (int i = tid; i < 2048; i += 512) {
        int o = i >> 5, r4 = (i & 31) << 2;
        float4 ov = *(float4*)&Ps[o * 132 + r4];
        int g = ((b * CC + o) * TT + t) * PP + q0 + r4;
        float4 xr = *(const float4*)&x_in[g];
        ov.x += xr.x; ov.y += xr.y; ov.z += xr.z; ov.w += xr.w;
        *(float4*)&out[g] = ov;
    }
}

// ---------------------------------------------------------------------------

extern "C" void kernel_launch(void* const* d_in, const int* in_sizes, int n_in,
                              void* d_out, int out_size) {
    const float* x_in = (const float*)d_in[0];
    const float* thw  = (const float*)d_in[1];
    const float* phw  = (const float*)d_in[2];
    const float* ow   = (const float*)d_in[3];
    float* out = (float*)d_out;

    const int prep_smem  = (CC * 256 + 128 * CC) * 4;                    // 98304 B
    const int flash_smem = (128 * 36 * 2 + 128 * 64 + 128 * 132) * 4;    // 137216 B

    cudaFuncSetAttribute(prep_kernel,  cudaFuncAttributeMaxDynamicSharedMemorySize, prep_smem);
    cudaFuncSetAttribute(flash_kernel, cudaFuncAttributeMaxDynamicSharedMemorySize, flash_smem);

    prep_kernel<<<dim3(NBT, PP / 256), 256, prep_smem>>>(x_in, thw, phw, ow);
    flash_kernel<<<dim3(PP / 128, NBT), 512, flash_smem>>>(x_in, out);
}